// round 2
// baseline (speedup 1.0000x reference)
#include <cuda_runtime.h>

#define NN 100000
#define NE 1600000
#define FD 128
#define NG 64
#define NC 32

// ---------------- scratch (static device globals; allocation-free) ----------
__device__ int   g_deg[NN];
__device__ int   g_offs[NN + 1];
__device__ int   g_cursor[NN];
__device__ int   g_col[NE];
__device__ float g_dinv[NN];
__device__ int   g_start[NG + 1];
__device__ float g_bufA[(size_t)NN * FD];   // GEMM output
__device__ float g_bufB[(size_t)NN * FD];   // agg/relu output
__device__ float g_pooled[NG * FD];

// ---------------- degree histogram ------------------------------------------
__global__ void k_zero_deg() {
    int i = blockIdx.x * blockDim.x + threadIdx.x;
    if (i < NN) g_deg[i] = 0;
}

__global__ void k_deg(const int* __restrict__ dst, int ne) {
    int i = blockIdx.x * blockDim.x + threadIdx.x;
    if (i < ne) atomicAdd(&g_deg[dst[i]], 1);
}

// ---------------- single-block exclusive scan (100k elems) ------------------
__global__ void k_scan(int n) {
    __shared__ int warp_sums[32];
    __shared__ int s_carry;
    int tid = threadIdx.x;
    if (tid == 0) s_carry = 0;
    __syncthreads();
    for (int base = 0; base < n; base += 1024) {
        int i = base + tid;
        int v = (i < n) ? g_deg[i] : 0;
        int x = v;
        #pragma unroll
        for (int d = 1; d < 32; d <<= 1) {
            int y = __shfl_up_sync(0xffffffffu, x, d);
            if ((tid & 31) >= d) x += y;
        }
        if ((tid & 31) == 31) warp_sums[tid >> 5] = x;
        __syncthreads();
        if (tid < 32) {
            int y = warp_sums[tid];
            #pragma unroll
            for (int d = 1; d < 32; d <<= 1) {
                int z = __shfl_up_sync(0xffffffffu, y, d);
                if (tid >= d) y += z;
            }
            warp_sums[tid] = y;
        }
        __syncthreads();
        int incl = x + ((tid >= 32) ? warp_sums[(tid >> 5) - 1] : 0);
        int excl = incl - v + s_carry;
        if (i < n) { g_offs[i] = excl; g_cursor[i] = excl; }
        __syncthreads();
        if (tid == 1023) s_carry += incl;  // block total (last thread's inclusive)
        __syncthreads();
    }
    if (tid == 0) g_offs[n] = s_carry;
}

__global__ void k_dinv() {
    int i = blockIdx.x * blockDim.x + threadIdx.x;
    if (i < NN) g_dinv[i] = rsqrtf((float)g_deg[i] + 1.0f);
}

// ---------------- CSR scatter ------------------------------------------------
__global__ void k_scatter(const int* __restrict__ src,
                          const int* __restrict__ dst, int ne) {
    int i = blockIdx.x * blockDim.x + threadIdx.x;
    if (i < ne) {
        int d = dst[i];
        int pos = atomicAdd(&g_cursor[d], 1);
        g_col[pos] = src[i];
    }
}

// ---------------- graph boundaries (batch is sorted) -------------------------
__global__ void k_start_init() {
    int i = threadIdx.x;
    if (i <= NG) g_start[i] = (i == NG) ? NN : 0x7fffffff;
}

__global__ void k_bound(const int* __restrict__ batch, int n) {
    int i = blockIdx.x * blockDim.x + threadIdx.x;
    if (i < n) {
        int b = batch[i];
        if (i == 0 || batch[i - 1] != b) atomicMin(&g_start[b], i);
    }
}

__global__ void k_fix_start() {
    for (int g = NG - 1; g >= 0; g--)
        if (g_start[g] == 0x7fffffff) g_start[g] = g_start[g + 1];
}

// ---------------- fp32 SIMT GEMM: C[n,128] = A[n,128] @ W[128,128] -----------
__global__ __launch_bounds__(256) void k_gemm(const float* __restrict__ A,
                                              const float* __restrict__ W,
                                              float* __restrict__ C, int nrows) {
    __shared__ float As[64][FD];   // 32 KB
    __shared__ float Ws[32][FD];   // 16 KB
    int row0 = blockIdx.x * 64;

    for (int i = threadIdx.x; i < 64 * 32; i += 256) {
        int r = i >> 5, c = i & 31;
        float4 v = make_float4(0.f, 0.f, 0.f, 0.f);
        if (row0 + r < nrows) v = ((const float4*)(A + (size_t)(row0 + r) * FD))[c];
        ((float4*)As[r])[c] = v;
    }

    int tx = threadIdx.x & 31;   // col group (4 cols)
    int ty = threadIdx.x >> 5;   // 8 row groups of 8
    float4 acc[8];
    #pragma unroll
    for (int rr = 0; rr < 8; rr++) acc[rr] = make_float4(0.f, 0.f, 0.f, 0.f);

    for (int kc = 0; kc < 4; kc++) {
        __syncthreads();
        for (int i = threadIdx.x; i < 32 * 32; i += 256) {
            int r = i >> 5, c = i & 31;
            ((float4*)Ws[r])[c] = ((const float4*)(W + (size_t)(kc * 32 + r) * FD))[c];
        }
        __syncthreads();
        #pragma unroll
        for (int k2 = 0; k2 < 32; k2++) {
            float4 w4 = ((float4*)Ws[k2])[tx];
            #pragma unroll
            for (int rr = 0; rr < 8; rr++) {
                float a = As[ty * 8 + rr][kc * 32 + k2];
                acc[rr].x = fmaf(a, w4.x, acc[rr].x);
                acc[rr].y = fmaf(a, w4.y, acc[rr].y);
                acc[rr].z = fmaf(a, w4.z, acc[rr].z);
                acc[rr].w = fmaf(a, w4.w, acc[rr].w);
            }
        }
    }
    #pragma unroll
    for (int rr = 0; rr < 8; rr++) {
        int r = row0 + ty * 8 + rr;
        if (r < nrows) ((float4*)(C + (size_t)r * FD))[tx] = acc[rr];
    }
}

// ---------------- GCN aggregation: warp per node, atomic-free ---------------
__global__ void k_agg(const float* __restrict__ h, const float* __restrict__ bias,
                      float* __restrict__ out) {
    int gw = (blockIdx.x * blockDim.x + threadIdx.x) >> 5;
    if (gw >= NN) return;
    int lane = threadIdx.x & 31;
    int node = gw;
    float di = g_dinv[node];
    int s = g_offs[node], e = g_offs[node + 1];
    float4 acc = make_float4(0.f, 0.f, 0.f, 0.f);
    for (int j = s; j < e; j++) {
        int sn = g_col[j];
        float w = di * g_dinv[sn];
        float4 hv = ((const float4*)(h + (size_t)sn * FD))[lane];
        acc.x = fmaf(w, hv.x, acc.x);
        acc.y = fmaf(w, hv.y, acc.y);
        acc.z = fmaf(w, hv.z, acc.z);
        acc.w = fmaf(w, hv.w, acc.w);
    }
    // self loop
    {
        float w = di * di;
        float4 hv = ((const float4*)(h + (size_t)node * FD))[lane];
        acc.x = fmaf(w, hv.x, acc.x);
        acc.y = fmaf(w, hv.y, acc.y);
        acc.z = fmaf(w, hv.z, acc.z);
        acc.w = fmaf(w, hv.w, acc.w);
    }
    float4 b4 = ((const float4*)bias)[lane];
    acc.x = fmaxf(acc.x + b4.x, 0.f);
    acc.y = fmaxf(acc.y + b4.y, 0.f);
    acc.z = fmaxf(acc.z + b4.z, 0.f);
    acc.w = fmaxf(acc.w + b4.w, 0.f);
    ((float4*)(out + (size_t)node * FD))[lane] = acc;
}

// ---------------- per-graph mean pool ----------------------------------------
__global__ void k_pool(const float* __restrict__ h) {
    int g = blockIdx.x;       // 64
    int c = threadIdx.x;      // 128
    int s = g_start[g], e = g_start[g + 1];
    float acc0 = 0.f, acc1 = 0.f, acc2 = 0.f, acc3 = 0.f;
    int i = s;
    for (; i + 4 <= e; i += 4) {
        acc0 += h[(size_t)(i + 0) * FD + c];
        acc1 += h[(size_t)(i + 1) * FD + c];
        acc2 += h[(size_t)(i + 2) * FD + c];
        acc3 += h[(size_t)(i + 3) * FD + c];
    }
    for (; i < e; i++) acc0 += h[(size_t)i * FD + c];
    float cnt = (float)((e - s) > 1 ? (e - s) : 1);
    g_pooled[g * FD + c] = (acc0 + acc1 + acc2 + acc3) / cnt;
}

// ---------------- final FC ----------------------------------------------------
__global__ void k_fc(const float* __restrict__ fcW, const float* __restrict__ fcb,
                     float* __restrict__ out) {
    int g = blockIdx.x;       // 64
    int c = threadIdx.x;      // 32
    float acc = fcb[c];
    #pragma unroll 4
    for (int k = 0; k < FD; k++)
        acc = fmaf(g_pooled[g * FD + k], fcW[k * NC + c], acc);
    out[g * NC + c] = acc;
}

// ---------------- launch ------------------------------------------------------
extern "C" void kernel_launch(void* const* d_in, const int* in_sizes, int n_in,
                              void* d_out, int out_size) {
    const float* x    = (const float*)d_in[0];
    const int*   ei   = (const int*)d_in[1];    // int64 in reference -> delivered as int32
    const int*   bat  = (const int*)d_in[2];
    const float* W1   = (const float*)d_in[3];
    const float* b1   = (const float*)d_in[4];
    const float* W2   = (const float*)d_in[5];
    const float* b2   = (const float*)d_in[6];
    const float* fcW  = (const float*)d_in[7];
    const float* fcb  = (const float*)d_in[8];
    float* out = (float*)d_out;

    int ne = in_sizes[1] / 2;
    const int* src = ei;
    const int* dst = ei + ne;

    float *bufA, *bufB;
    cudaGetSymbolAddress((void**)&bufA, g_bufA);
    cudaGetSymbolAddress((void**)&bufB, g_bufB);

    int tb = 256;
    int gbN  = (NN + tb - 1) / tb;
    int gbE  = (ne + tb - 1) / tb;
    int gbAgg = (NN * 32 + tb - 1) / tb;     // warp per node
    int gbGemm = (NN + 63) / 64;

    // CSR build + degrees (same for both layers)
    k_zero_deg<<<gbN, tb>>>();
    k_deg<<<gbE, tb>>>(dst, ne);
    k_scan<<<1, 1024>>>(NN);
    k_dinv<<<gbN, tb>>>();
    k_scatter<<<gbE, tb>>>(src, dst, ne);

    // graph boundaries for pooling
    k_start_init<<<1, NG + 1>>>();
    k_bound<<<gbN, tb>>>(bat, NN);
    k_fix_start<<<1, 1>>>();

    // layer 1
    k_gemm<<<gbGemm, tb>>>(x, W1, bufA, NN);
    k_agg<<<gbAgg, tb>>>(bufA, b1, bufB);
    // layer 2
    k_gemm<<<gbGemm, tb>>>(bufB, W2, bufA, NN);
    k_agg<<<gbAgg, tb>>>(bufA, b2, bufB);

    // pool + fc
    k_pool<<<NG, FD>>>(bufB);
    k_fc<<<NG, NC>>>(fcW, fcb, out);
}

// round 3
// speedup vs baseline: 1.0689x; 1.0689x over previous
#include <cuda_runtime.h>
#include <cstdint>

#define NN 100000
#define NE 1600000
#define FD 128
#define NG 64
#define NC 32

#define NBLK ((NN + 255) / 256)   // 391 scan blocks

// ---------------- scratch (static device globals; allocation-free) ----------
__device__ int   g_deg[NN];
__device__ int   g_offs[NN + 1];
__device__ int   g_cursor[NN];
__device__ int   g_col[NE];
__device__ float g_dinv[NN];
__device__ int   g_start[NG + 1];
__device__ int   g_bsum[NBLK];
__device__ float g_bufA[(size_t)NN * FD];
__device__ float g_bufB[(size_t)NN * FD];
__device__ float g_pooled[NG * FD];
__device__ float g_W1hi[FD * FD], g_W1lo[FD * FD];
__device__ float g_W2hi[FD * FD], g_W2lo[FD * FD];

// ---------------- helpers -----------------------------------------------------
__device__ __forceinline__ uint32_t f2tf32(float x) {
    uint32_t r; asm("cvt.rna.tf32.f32 %0, %1;" : "=r"(r) : "f"(x)); return r;
}

__device__ __forceinline__ void mma_tf32(float* d, const uint32_t* a, uint32_t b0, uint32_t b1) {
    asm volatile("mma.sync.aligned.m16n8k8.row.col.f32.tf32.tf32.f32 "
                 "{%0,%1,%2,%3}, {%4,%5,%6,%7}, {%8,%9}, {%0,%1,%2,%3};"
                 : "+f"(d[0]), "+f"(d[1]), "+f"(d[2]), "+f"(d[3])
                 : "r"(a[0]), "r"(a[1]), "r"(a[2]), "r"(a[3]), "r"(b0), "r"(b1));
}

// ---------------- init: zero deg + start sentinel ----------------------------
__global__ void k_init() {
    int i = blockIdx.x * blockDim.x + threadIdx.x;
    if (i < NN) g_deg[i] = 0;
    if (i <= NG) g_start[i] = (i == NG) ? NN : 0x7fffffff;
}

__global__ void k_deg(const int* __restrict__ dst, int ne) {
    int i = blockIdx.x * blockDim.x + threadIdx.x;
    if (i < ne) atomicAdd(&g_deg[dst[i]], 1);
}

// ---------------- W hi/lo split (tf32 3-term) ---------------------------------
__global__ void k_wsplit(const float* __restrict__ W, float* __restrict__ Whi,
                         float* __restrict__ Wlo) {
    int i = blockIdx.x * blockDim.x + threadIdx.x;
    if (i < FD * FD) {
        float w = W[i];
        float hf = __uint_as_float(f2tf32(w));
        Whi[i] = hf;
        Wlo[i] = __uint_as_float(f2tf32(w - hf));
    }
}

// ---------------- 3-phase scan ------------------------------------------------
__global__ void k_blocksum() {
    __shared__ int s[256];
    int i = blockIdx.x * 256 + threadIdx.x;
    s[threadIdx.x] = (i < NN) ? g_deg[i] : 0;
    __syncthreads();
    for (int d = 128; d > 0; d >>= 1) {
        if (threadIdx.x < d) s[threadIdx.x] += s[threadIdx.x + d];
        __syncthreads();
    }
    if (threadIdx.x == 0) g_bsum[blockIdx.x] = s[0];
}

__global__ void k_scanpartials() {
    __shared__ int s[512];
    int tid = threadIdx.x;
    s[tid] = (tid < NBLK) ? g_bsum[tid] : 0;
    __syncthreads();
    // Hillis-Steele inclusive
    for (int d = 1; d < 512; d <<= 1) {
        int v = (tid >= d) ? s[tid - d] : 0;
        __syncthreads();
        s[tid] += v;
        __syncthreads();
    }
    if (tid < NBLK) g_bsum[tid] = s[tid] - ((tid < NBLK) ? g_deg[0] * 0 : 0) - (s[tid] - (tid ? s[tid - 1] : 0)); // exclusive = inclusive - self
    if (tid == 0) g_offs[NN] = s[511];
}

__global__ void k_offsets() {
    __shared__ int warp_sums[8];
    int tid = threadIdx.x;
    int i = blockIdx.x * 256 + tid;
    int v = (i < NN) ? g_deg[i] : 0;
    int x = v;
    #pragma unroll
    for (int d = 1; d < 32; d <<= 1) {
        int y = __shfl_up_sync(0xffffffffu, x, d);
        if ((tid & 31) >= d) x += y;
    }
    if ((tid & 31) == 31) warp_sums[tid >> 5] = x;
    __syncthreads();
    if (tid < 8) {
        int y = warp_sums[tid];
        #pragma unroll
        for (int d = 1; d < 8; d <<= 1) {
            int z = __shfl_up_sync(0xffu, y, d);
            if (tid >= d) y += z;
        }
        warp_sums[tid] = y;
    }
    __syncthreads();
    int incl = x + ((tid >= 32) ? warp_sums[(tid >> 5) - 1] : 0);
    int excl = incl - v + g_bsum[blockIdx.x];
    if (i < NN) {
        g_offs[i] = excl;
        g_cursor[i] = excl;
        g_dinv[i] = rsqrtf((float)v + 1.0f);
    }
}

// ---------------- CSR scatter --------------------------------------------------
__global__ void k_scatter(const int* __restrict__ src,
                          const int* __restrict__ dst, int ne) {
    int i = blockIdx.x * blockDim.x + threadIdx.x;
    if (i < ne) {
        int d = dst[i];
        int pos = atomicAdd(&g_cursor[d], 1);
        g_col[pos] = src[i];
    }
}

// ---------------- graph boundaries ---------------------------------------------
__global__ void k_bound(const int* __restrict__ batch, int n) {
    int i = blockIdx.x * blockDim.x + threadIdx.x;
    if (i < n) {
        int b = batch[i];
        if (i == 0 || batch[i - 1] != b) atomicMin(&g_start[b], i);
    }
}

__global__ void k_fix_start() {
    for (int g = NG - 1; g >= 0; g--)
        if (g_start[g] == 0x7fffffff) g_start[g] = g_start[g + 1];
}

// ---------------- tf32 tensor-core GEMM: C[n,128] = A[n,128] @ W[128,128] ------
// 3-term split: A = Ah + Al (in-kernel), W pre-split hi/lo in global.
// Block: 128 rows x 128 cols, 256 threads (8 warps, warp = 32 rows x 64 cols).
#define AS_STRIDE 132
#define WS_STRIDE 136
#define SMEM_AS_BYTES (128 * AS_STRIDE * 4)
#define SMEM_WS_BYTES (128 * WS_STRIDE * 4)
#define GEMM_SMEM (SMEM_AS_BYTES + 2 * SMEM_WS_BYTES)

__global__ __launch_bounds__(256) void k_gemm_tf32(const float* __restrict__ A,
                                                   const float* __restrict__ Whi,
                                                   const float* __restrict__ Wlo,
                                                   float* __restrict__ C, int nrows) {
    extern __shared__ float smem[];
    float* As = smem;                                  // [128][132]
    float* Wh = smem + 128 * AS_STRIDE;                // [128][136]
    float* Wl = Wh + 128 * WS_STRIDE;                  // [128][136]

    int tid = threadIdx.x;
    int row0 = blockIdx.x * 128;

    // load A tile (guarded, float4)
    for (int i = tid; i < 128 * 32; i += 256) {
        int r = i >> 5, c = i & 31;
        float4 v = make_float4(0.f, 0.f, 0.f, 0.f);
        if (row0 + r < nrows) v = ((const float4*)(A + (size_t)(row0 + r) * FD))[c];
        float* dstp = As + r * AS_STRIDE + c * 4;
        dstp[0] = v.x; dstp[1] = v.y; dstp[2] = v.z; dstp[3] = v.w;
    }
    // load W hi/lo tiles (full 128x128)
    for (int i = tid; i < 128 * 32; i += 256) {
        int r = i >> 5, c = i & 31;
        float4 vh = ((const float4*)(Whi + (size_t)r * FD))[c];
        float4 vl = ((const float4*)(Wlo + (size_t)r * FD))[c];
        float* dh = Wh + r * WS_STRIDE + c * 4;
        float* dl = Wl + r * WS_STRIDE + c * 4;
        dh[0] = vh.x; dh[1] = vh.y; dh[2] = vh.z; dh[3] = vh.w;
        dl[0] = vl.x; dl[1] = vl.y; dl[2] = vl.z; dl[3] = vl.w;
    }
    __syncthreads();

    int lane = tid & 31;
    int wid  = tid >> 5;
    int wr = wid & 3;        // row group: rows 32*wr .. 32*wr+31
    int wc = wid >> 2;       // col group: cols 64*wc .. 64*wc+63

    float acc[2][8][4];
    #pragma unroll
    for (int s = 0; s < 2; s++)
        #pragma unroll
        for (int t = 0; t < 8; t++)
            #pragma unroll
            for (int q = 0; q < 4; q++) acc[s][t][q] = 0.f;

    int qrow = lane >> 2;    // 0..7
    int qcol = lane & 3;     // 0..3

    #pragma unroll 2
    for (int kk = 0; kk < 16; kk++) {
        int k0 = kk * 8;
        // A fragments: 2 m16 subtiles, hi/lo split in registers
        uint32_t ah[2][4], al[2][4];
        #pragma unroll
        for (int s = 0; s < 2; s++) {
            int rb = 32 * wr + 16 * s + qrow;
            float a0 = As[(rb)     * AS_STRIDE + k0 + qcol];
            float a1 = As[(rb + 8) * AS_STRIDE + k0 + qcol];
            float a2 = As[(rb)     * AS_STRIDE + k0 + qcol + 4];
            float a3 = As[(rb + 8) * AS_STRIDE + k0 + qcol + 4];
            float f;
            ah[s][0] = f2tf32(a0); f = __uint_as_float(ah[s][0]); al[s][0] = f2tf32(a0 - f);
            ah[s][1] = f2tf32(a1); f = __uint_as_float(ah[s][1]); al[s][1] = f2tf32(a1 - f);
            ah[s][2] = f2tf32(a2); f = __uint_as_float(ah[s][2]); al[s][2] = f2tf32(a2 - f);
            ah[s][3] = f2tf32(a3); f = __uint_as_float(ah[s][3]); al[s][3] = f2tf32(a3 - f);
        }
        int kb = k0 + qcol;
        #pragma unroll
        for (int t = 0; t < 8; t++) {
            int n = 64 * wc + 8 * t + qrow;
            uint32_t bh0 = __float_as_uint(Wh[(kb)     * WS_STRIDE + n]);
            uint32_t bh1 = __float_as_uint(Wh[(kb + 4) * WS_STRIDE + n]);
            uint32_t bl0 = __float_as_uint(Wl[(kb)     * WS_STRIDE + n]);
            uint32_t bl1 = __float_as_uint(Wl[(kb + 4) * WS_STRIDE + n]);
            #pragma unroll
            for (int s = 0; s < 2; s++) {
                mma_tf32(acc[s][t], ah[s], bh0, bh1);
                mma_tf32(acc[s][t], al[s], bh0, bh1);
                mma_tf32(acc[s][t], ah[s], bl0, bl1);
            }
        }
    }

    // epilogue: float2 stores, guarded rows
    #pragma unroll
    for (int s = 0; s < 2; s++) {
        int rbase = row0 + 32 * wr + 16 * s + qrow;
        #pragma unroll
        for (int t = 0; t < 8; t++) {
            int col = 64 * wc + 8 * t + 2 * qcol;
            if (rbase < nrows)
                *(float2*)(C + (size_t)rbase * FD + col) = make_float2(acc[s][t][0], acc[s][t][1]);
            if (rbase + 8 < nrows)
                *(float2*)(C + (size_t)(rbase + 8) * FD + col) = make_float2(acc[s][t][2], acc[s][t][3]);
        }
    }
}

// ---------------- GCN aggregation: warp per node, atomic-free ------------------
__global__ void k_agg(const float* __restrict__ h, const float* __restrict__ bias,
                      float* __restrict__ out) {
    int gw = (blockIdx.x * blockDim.x + threadIdx.x) >> 5;
    if (gw >= NN) return;
    int lane = threadIdx.x & 31;
    int node = gw;
    float di = g_dinv[node];
    int s = g_offs[node], e = g_offs[node + 1];
    float4 acc = make_float4(0.f, 0.f, 0.f, 0.f);
    #pragma unroll 4
    for (int j = s; j < e; j++) {
        int sn = g_col[j];
        float w = di * g_dinv[sn];
        float4 hv = ((const float4*)(h + (size_t)sn * FD))[lane];
        acc.x = fmaf(w, hv.x, acc.x);
        acc.y = fmaf(w, hv.y, acc.y);
        acc.z = fmaf(w, hv.z, acc.z);
        acc.w = fmaf(w, hv.w, acc.w);
    }
    {   // self loop
        float w = di * di;
        float4 hv = ((const float4*)(h + (size_t)node * FD))[lane];
        acc.x = fmaf(w, hv.x, acc.x);
        acc.y = fmaf(w, hv.y, acc.y);
        acc.z = fmaf(w, hv.z, acc.z);
        acc.w = fmaf(w, hv.w, acc.w);
    }
    float4 b4 = ((const float4*)bias)[lane];
    acc.x = fmaxf(acc.x + b4.x, 0.f);
    acc.y = fmaxf(acc.y + b4.y, 0.f);
    acc.z = fmaxf(acc.z + b4.z, 0.f);
    acc.w = fmaxf(acc.w + b4.w, 0.f);
    ((float4*)(out + (size_t)node * FD))[lane] = acc;
}

// ---------------- per-graph mean pool ------------------------------------------
__global__ void k_pool(const float* __restrict__ h) {
    int g = blockIdx.x;
    int c = threadIdx.x;
    int s = g_start[g], e = g_start[g + 1];
    float acc0 = 0.f, acc1 = 0.f, acc2 = 0.f, acc3 = 0.f;
    int i = s;
    for (; i + 4 <= e; i += 4) {
        acc0 += h[(size_t)(i + 0) * FD + c];
        acc1 += h[(size_t)(i + 1) * FD + c];
        acc2 += h[(size_t)(i + 2) * FD + c];
        acc3 += h[(size_t)(i + 3) * FD + c];
    }
    for (; i < e; i++) acc0 += h[(size_t)i * FD + c];
    float cnt = (float)((e - s) > 1 ? (e - s) : 1);
    g_pooled[g * FD + c] = (acc0 + acc1 + acc2 + acc3) / cnt;
}

// ---------------- final FC -------------------------------------------------------
__global__ void k_fc(const float* __restrict__ fcW, const float* __restrict__ fcb,
                     float* __restrict__ out) {
    int g = blockIdx.x;
    int c = threadIdx.x;
    float acc = fcb[c];
    #pragma unroll 4
    for (int k = 0; k < FD; k++)
        acc = fmaf(g_pooled[g * FD + k], fcW[k * NC + c], acc);
    out[g * NC + c] = acc;
}

// ---------------- launch ----------------------------------------------------------
extern "C" void kernel_launch(void* const* d_in, const int* in_sizes, int n_in,
                              void* d_out, int out_size) {
    const float* x    = (const float*)d_in[0];
    const int*   ei   = (const int*)d_in[1];
    const int*   bat  = (const int*)d_in[2];
    const float* W1   = (const float*)d_in[3];
    const float* b1   = (const float*)d_in[4];
    const float* W2   = (const float*)d_in[5];
    const float* b2   = (const float*)d_in[6];
    const float* fcW  = (const float*)d_in[7];
    const float* fcb  = (const float*)d_in[8];
    float* out = (float*)d_out;

    int ne = in_sizes[1] / 2;
    const int* src = ei;
    const int* dst = ei + ne;

    float *bufA, *bufB, *w1h, *w1l, *w2h, *w2l;
    cudaGetSymbolAddress((void**)&bufA, g_bufA);
    cudaGetSymbolAddress((void**)&bufB, g_bufB);
    cudaGetSymbolAddress((void**)&w1h, g_W1hi);
    cudaGetSymbolAddress((void**)&w1l, g_W1lo);
    cudaGetSymbolAddress((void**)&w2h, g_W2hi);
    cudaGetSymbolAddress((void**)&w2l, g_W2lo);

    static bool attr_set = false;
    if (!attr_set) {
        cudaFuncSetAttribute(k_gemm_tf32, cudaFuncAttributeMaxDynamicSharedMemorySize, GEMM_SMEM);
        attr_set = true;
    }

    int tb = 256;
    int gbN   = (NN + tb - 1) / tb;
    int gbE   = (ne + tb - 1) / tb;
    int gbAgg = (NN * 32 + tb - 1) / tb;
    int gbGemm = (NN + 127) / 128;

    // setup
    k_init<<<gbN, tb>>>();
    k_deg<<<gbE, tb>>>(dst, ne);
    k_wsplit<<<(FD * FD + tb - 1) / tb, tb>>>(W1, w1h, w1l);
    k_wsplit<<<(FD * FD + tb - 1) / tb, tb>>>(W2, w2h, w2l);
    k_blocksum<<<NBLK, tb>>>();
    k_scanpartials<<<1, 512>>>();
    k_offsets<<<NBLK, tb>>>();
    k_scatter<<<gbE, tb>>>(src, dst, ne);
    k_bound<<<gbN, tb>>>(bat, NN);
    k_fix_start<<<1, 1>>>();

    // layer 1
    k_gemm_tf32<<<gbGemm, tb, GEMM_SMEM>>>(x, w1h, w1l, bufA, NN);
    k_agg<<<gbAgg, tb>>>(bufA, b1, bufB);
    // layer 2
    k_gemm_tf32<<<gbGemm, tb, GEMM_SMEM>>>(bufB, w2h, w2l, bufA, NN);
    k_agg<<<gbAgg, tb>>>(bufA, b2, bufB);

    // pool + fc
    k_pool<<<NG, FD>>>(bufB);
    k_fc<<<NG, NC>>>(fcW, fcb, out);
}